// round 9
// baseline (speedup 1.0000x reference)
#include <cuda_runtime.h>
#include <cuda_fp16.h>
#include <cstdint>
#include <math_constants.h>

#define NND 40000
#define HD  128
#define EED 640000

// ---------------- scratch (device globals: allocation-free) ----------------
__device__ __half   g_bufXW [(size_t)NND * HD];   // GCN GEMM out, fp16 (gathered)
__device__ __half   g_bufHH [(size_t)NND * HD];   // GAT GEMM out, fp16 (gathered)
__device__ float    g_bufACC[(size_t)NND * HD];   // relu(GCN) out, fp32 (GEMM input)
__device__ float    g_bufOUT[(size_t)NND * HD];   // GAT out, fp32 (GEMM input / pool)
__device__ int      g_deg   [NND];
__device__ float    g_dinv  [NND];
__device__ int      g_rowptr[NND];
__device__ int      g_cursor[NND];
__device__ int      g_rowtmp[NND];
__device__ int      g_bsum  [256];
__device__ int      g_boff  [256];
__device__ int      g_csrcol[EED];
__device__ uint32_t g_Bperm [6 * HD * HD];        // 6 permuted weights (all layers)

// ---------------- helpers ----------------
__device__ __forceinline__ float4 h8_to_f4(uint2 u) {
    __half2 a = *(__half2*)&u.x, b = *(__half2*)&u.y;
    float2 fa = __half22float2(a), fb = __half22float2(b);
    return make_float4(fa.x, fa.y, fb.x, fb.y);
}

// ---------------- degree / norm ----------------
__global__ void k_deg_init() {
    int i = blockIdx.x * blockDim.x + threadIdx.x;
    if (i < NND) g_deg[i] = 1;
}
__global__ void k_deg_count(const int* __restrict__ row, int E) {
    int e = blockIdx.x * blockDim.x + threadIdx.x;
    if (e < E) atomicAdd(&g_deg[row[e]], 1);
}

// ---------------- hierarchical exclusive scan of (deg-1), + dinv ----------------
__global__ __launch_bounds__(256) void k_scanA() {
    __shared__ int sm[256];
    int tx = threadIdx.x;
    int i = blockIdx.x * 256 + tx;
    int d = (i < NND) ? g_deg[i] : 1;
    if (i < NND) g_dinv[i] = rsqrtf((float)d);
    int v = d - 1;
    if (i >= NND) v = 0;
    sm[tx] = v;
    __syncthreads();
#pragma unroll
    for (int off = 1; off < 256; off <<= 1) {
        int p = (tx >= off) ? sm[tx - off] : 0;
        __syncthreads();
        sm[tx] += p;
        __syncthreads();
    }
    if (i < NND) g_rowtmp[i] = sm[tx] - v;
    if (tx == 255) g_bsum[blockIdx.x] = sm[255];
}
__global__ __launch_bounds__(256) void k_scanB(int nb) {
    __shared__ int sm[256];
    int tx = threadIdx.x;
    int v = (tx < nb) ? g_bsum[tx] : 0;
    sm[tx] = v;
    __syncthreads();
#pragma unroll
    for (int off = 1; off < 256; off <<= 1) {
        int p = (tx >= off) ? sm[tx - off] : 0;
        __syncthreads();
        sm[tx] += p;
        __syncthreads();
    }
    g_boff[tx] = sm[tx] - v;
}
__global__ void k_scanC() {
    int i = blockIdx.x * blockDim.x + threadIdx.x;
    if (i < NND) {
        int rp = g_rowtmp[i] + g_boff[i >> 8];
        g_rowptr[i] = rp;
        g_cursor[i] = rp;
    }
}
__global__ void k_fill(const int* __restrict__ row, const int* __restrict__ col, int E) {
    int e = blockIdx.x * blockDim.x + threadIdx.x;
    if (e >= E) return;
    int r = row[e];
    int pos = atomicAdd(&g_cursor[r], 1);
    g_csrcol[pos] = col[e];
}

// ---------------- all-weights preconvert: (fold) + tf32 + fragment permute ----------
__device__ __forceinline__ uint32_t f2tf32(float f) {
    uint32_t u;
    asm("cvt.rna.tf32.f32 %0, %1;" : "=r"(u) : "f"(f));
    return u;
}
// slot s: 0..5 = Wg0,Wa0,Wg1,Wa1,Wg2,Wa2 ; fold for slots 2,4 (Wg1,Wg2)
__global__ void k_bperm_all(const float* __restrict__ W0, const float* __restrict__ W1,
                            const float* __restrict__ W2, const float* __restrict__ W3,
                            const float* __restrict__ W4, const float* __restrict__ W5) {
    int s = blockIdx.y;
    const float* W;
    int fold = 0;
    switch (s) {
        case 0: W = W0; break;
        case 1: W = W1; break;
        case 2: W = W2; fold = 1; break;
        case 3: W = W3; break;
        case 4: W = W4; fold = 1; break;
        default: W = W5; break;
    }
    int t = blockIdx.x * blockDim.x + threadIdx.x;
    if (t >= HD * HD) return;
    int k = t >> 7, n = t & 127;
    float v = W[t];
    if (fold) v += W[t + HD * HD];
    int ki = k >> 3, ni = n >> 3, kk = k & 7, nn = n & 7;
    int l = (nn << 2) | (kk & 3);
    int j = kk >> 2;
    g_Bperm[s * HD * HD + (ki * 16 + ni) * 64 + l * 2 + j] = f2tf32(v);
}

// ---------------- TF32 tensor-core GEMM: Ch[M,128] = A[M,128] @ Bperm[slot] ---------
__device__ __forceinline__ void mma_tf32(float* d, const uint32_t* a, const uint32_t* b) {
    asm volatile(
        "mma.sync.aligned.m16n8k8.row.col.f32.tf32.tf32.f32 "
        "{%0,%1,%2,%3}, {%4,%5,%6,%7}, {%8,%9}, {%0,%1,%2,%3};"
        : "+f"(d[0]), "+f"(d[1]), "+f"(d[2]), "+f"(d[3])
        : "r"(a[0]), "r"(a[1]), "r"(a[2]), "r"(a[3]), "r"(b[0]), "r"(b[1]));
}
__global__ __launch_bounds__(256) void k_gemm_tf32(const float* __restrict__ A,
                                                   const float* __restrict__ bias,
                                                   const float* __restrict__ rowscale,
                                                   __half* __restrict__ Ch, int M, int slot) {
    __shared__ uint32_t Asp[32 * 128];
    const uint32_t* Bp = g_Bperm + slot * HD * HD;
    int tid = threadIdx.x;
    int lane = tid & 31;
    int w = tid >> 5;
    int wm = w >> 2, wn = w & 3;
    int gRow0 = blockIdx.x * 128;
    float acc[4][4][4];
#pragma unroll
    for (int i = 0; i < 4; i++)
#pragma unroll
        for (int t = 0; t < 4; t++)
#pragma unroll
            for (int u = 0; u < 4; u++) acc[i][t][u] = 0.f;

    for (int kk = 0; kk < 128; kk += 32) {
#pragma unroll
        for (int q = 0; q < 4; q++) {
            int fid = tid + q * 256;
            int row = fid >> 3;
            int c4  = fid & 7;
            int gr  = gRow0 + row;
            float4 v = make_float4(0.f, 0.f, 0.f, 0.f);
            if (gr < M) v = *(const float4*)(A + (size_t)gr * 128 + kk + c4 * 4);
            int mi = row >> 4, rr = row & 15;
            int ki = c4 >> 1;
            int j  = (rr >> 3) | ((c4 & 1) << 1);
            uint4 o;
            o.x = f2tf32(v.x); o.y = f2tf32(v.y); o.z = f2tf32(v.z); o.w = f2tf32(v.w);
            *(uint4*)(&Asp[(ki * 8 + mi) * 128 + j * 32 + (rr & 7) * 4]) = o;
        }
        __syncthreads();
#pragma unroll
        for (int ki = 0; ki < 4; ki++) {
            uint32_t af[4][4];
#pragma unroll
            for (int i = 0; i < 4; i++) {
                const uint32_t* base = &Asp[(ki * 8 + wm * 4 + i) * 128];
                af[i][0] = base[lane];
                af[i][1] = base[32 + lane];
                af[i][2] = base[64 + lane];
                af[i][3] = base[96 + lane];
            }
            uint32_t bf[4][2];
            int kig = (kk >> 3) + ki;
#pragma unroll
            for (int t = 0; t < 4; t++) {
                uint2 b2 = *(const uint2*)(&Bp[(kig * 16 + wn * 4 + t) * 64 + lane * 2]);
                bf[t][0] = b2.x; bf[t][1] = b2.y;
            }
#pragma unroll
            for (int i = 0; i < 4; i++)
#pragma unroll
                for (int t = 0; t < 4; t++) mma_tf32(acc[i][t], af[i], bf[t]);
        }
        __syncthreads();
    }
    int g = lane >> 2, t4 = lane & 3;
#pragma unroll
    for (int i = 0; i < 4; i++) {
        int row0 = gRow0 + (wm * 4 + i) * 16 + g;
        int row1 = row0 + 8;
        float rs0 = 1.f, rs1 = 1.f;
        if (rowscale) {
            if (row0 < M) rs0 = rowscale[row0];
            if (row1 < M) rs1 = rowscale[row1];
        }
#pragma unroll
        for (int t = 0; t < 4; t++) {
            int col = (wn * 4 + t) * 8 + 2 * t4;
            float b0 = bias ? bias[col] : 0.f;
            float b1 = bias ? bias[col + 1] : 0.f;
            if (row0 < M)
                *(__half2*)(Ch + (size_t)row0 * 128 + col) =
                    __floats2half2_rn((acc[i][t][0] + b0) * rs0, (acc[i][t][1] + b1) * rs0);
            if (row1 < M)
                *(__half2*)(Ch + (size_t)row1 * 128 + col) =
                    __floats2half2_rn((acc[i][t][2] + b0) * rs1, (acc[i][t][3] + b1) * rs1);
        }
    }
}

// ---------------- fused GCN (warp per node, 2 accumulators) ----------------
__global__ __launch_bounds__(256) void k_gcn(const float* __restrict__ bias) {
    int r = (blockIdx.x * blockDim.x + threadIdx.x) >> 5;
    int lane = threadIdx.x & 31;
    if (r >= NND) return;
    int beg = g_rowptr[r];
    int cnt = g_deg[r] - 1;
    float dr = g_dinv[r];
    const __half* xw = g_bufXW;
    float4 acc = h8_to_f4(*(const uint2*)(xw + (size_t)r * HD + lane * 4));
    float4 acc2 = make_float4(0.f, 0.f, 0.f, 0.f);
    int j = 0;
    for (; j + 8 <= cnt; j += 8) {
        uint2 u[8];
#pragma unroll
        for (int q = 0; q < 8; q++) {
            int c = g_csrcol[beg + j + q];
            u[q] = *(const uint2*)(xw + (size_t)c * HD + lane * 4);
        }
#pragma unroll
        for (int q = 0; q < 8; q += 2) {
            float4 v0 = h8_to_f4(u[q]);
            float4 v1 = h8_to_f4(u[q + 1]);
            acc.x += v0.x; acc.y += v0.y; acc.z += v0.z; acc.w += v0.w;
            acc2.x += v1.x; acc2.y += v1.y; acc2.z += v1.z; acc2.w += v1.w;
        }
    }
    for (; j < cnt; j++) {
        int c = g_csrcol[beg + j];
        float4 v = h8_to_f4(*(const uint2*)(xw + (size_t)c * HD + lane * 4));
        acc.x += v.x; acc.y += v.y; acc.z += v.z; acc.w += v.w;
    }
    acc.x += acc2.x; acc.y += acc2.y; acc.z += acc2.z; acc.w += acc2.w;
    float4 b = *(const float4*)(bias + lane * 4);
    acc.x = fmaxf(acc.x * dr + b.x, 0.f);
    acc.y = fmaxf(acc.y * dr + b.y, 0.f);
    acc.z = fmaxf(acc.z * dr + b.z, 0.f);
    acc.w = fmaxf(acc.w * dr + b.w, 0.f);
    *(float4*)(g_bufACC + (size_t)r * HD + lane * 4) = acc;
}

// ---------------- fused GAT: dual-state online softmax (warp per node) --------------
__device__ __forceinline__ float warp_sum(float s) {
#pragma unroll
    for (int o = 16; o; o >>= 1) s += __shfl_xor_sync(0xffffffffu, s, o);
    return s;
}
__global__ __launch_bounds__(256) void k_gat() {
    int r = (blockIdx.x * blockDim.x + threadIdx.x) >> 5;
    int lane = threadIdx.x & 31;
    if (r >= NND) return;
    int beg = g_rowptr[r];
    int cnt = g_deg[r] - 1;
    const __half* hh = g_bufHH;
    float4 hr = h8_to_f4(*(const uint2*)(hh + (size_t)r * HD + lane * 4));
    // state A seeded with the appended self loop; state B empty
    float mA = warp_sum(hr.x * hr.x + hr.y * hr.y + hr.z * hr.z + hr.w * hr.w);
    float dA = 1.f;
    float4 aA = hr;
    float mB = -CUDART_INF_F;
    float dB = 0.f;
    float4 aB = make_float4(0.f, 0.f, 0.f, 0.f);
    int j = 0;
    for (; j + 4 <= cnt; j += 4) {
        int c0 = g_csrcol[beg + j];
        int c1 = g_csrcol[beg + j + 1];
        int c2 = g_csrcol[beg + j + 2];
        int c3 = g_csrcol[beg + j + 3];
        float4 h0 = h8_to_f4(*(const uint2*)(hh + (size_t)c0 * HD + lane * 4));
        float4 h1 = h8_to_f4(*(const uint2*)(hh + (size_t)c1 * HD + lane * 4));
        float4 h2 = h8_to_f4(*(const uint2*)(hh + (size_t)c2 * HD + lane * 4));
        float4 h3 = h8_to_f4(*(const uint2*)(hh + (size_t)c3 * HD + lane * 4));
        float d0 = hr.x * h0.x + hr.y * h0.y + hr.z * h0.z + hr.w * h0.w;
        float d1 = hr.x * h1.x + hr.y * h1.y + hr.z * h1.z + hr.w * h1.w;
        float d2 = hr.x * h2.x + hr.y * h2.y + hr.z * h2.z + hr.w * h2.w;
        float d3 = hr.x * h3.x + hr.y * h3.y + hr.z * h3.z + hr.w * h3.w;
#pragma unroll
        for (int o = 16; o; o >>= 1) {
            d0 += __shfl_xor_sync(0xffffffffu, d0, o);
            d1 += __shfl_xor_sync(0xffffffffu, d1, o);
            d2 += __shfl_xor_sync(0xffffffffu, d2, o);
            d3 += __shfl_xor_sync(0xffffffffu, d3, o);
        }
        float a0 = (c0 == r) ? -CUDART_INF_F : ((d0 > 0.f) ? d0 : 0.2f * d0);
        float a1 = (c1 == r) ? -CUDART_INF_F : ((d1 > 0.f) ? d1 : 0.2f * d1);
        float a2 = (c2 == r) ? -CUDART_INF_F : ((d2 > 0.f) ? d2 : 0.2f * d2);
        float a3 = (c3 == r) ? -CUDART_INF_F : ((d3 > 0.f) ? d3 : 0.2f * d3);
        // state A takes edges 0,1 ; state B takes edges 2,3 (independent chains)
        {
            float mn = fmaxf(mA, fmaxf(a0, a1));
            float s = __expf(mA - mn);
            float e0 = __expf(a0 - mn);
            float e1 = __expf(a1 - mn);
            dA = dA * s + (e0 + e1);
            aA.x = aA.x * s + e0 * h0.x + e1 * h1.x;
            aA.y = aA.y * s + e0 * h0.y + e1 * h1.y;
            aA.z = aA.z * s + e0 * h0.z + e1 * h1.z;
            aA.w = aA.w * s + e0 * h0.w + e1 * h1.w;
            mA = mn;
        }
        {
            float mn = fmaxf(mB, fmaxf(a2, a3));
            float s = (mB == -CUDART_INF_F) ? 0.f : __expf(mB - mn);
            float e2 = __expf(a2 - mn);
            float e3 = __expf(a3 - mn);
            dB = dB * s + (e2 + e3);
            aB.x = aB.x * s + e2 * h2.x + e3 * h3.x;
            aB.y = aB.y * s + e2 * h2.y + e3 * h3.y;
            aB.z = aB.z * s + e2 * h2.z + e3 * h3.z;
            aB.w = aB.w * s + e2 * h2.w + e3 * h3.w;
            mB = mn;
        }
    }
    for (; j < cnt; j++) {
        int c = g_csrcol[beg + j];
        if (c == r) continue;
        float4 hc = h8_to_f4(*(const uint2*)(hh + (size_t)c * HD + lane * 4));
        float d = warp_sum(hr.x * hc.x + hr.y * hc.y + hr.z * hc.z + hr.w * hc.w);
        float al = (d > 0.f) ? d : 0.2f * d;
        float mn = fmaxf(mA, al);
        float s = __expf(mA - mn);
        float e = __expf(al - mn);
        dA = dA * s + e;
        aA.x = aA.x * s + e * hc.x;
        aA.y = aA.y * s + e * hc.y;
        aA.z = aA.z * s + e * hc.z;
        aA.w = aA.w * s + e * hc.w;
        mA = mn;
    }
    // merge state B into A (B may be empty: dB==0, mB==-inf -> sB=0)
    {
        float mn = fmaxf(mA, mB);
        float sA = __expf(mA - mn);
        float sB = (mB == -CUDART_INF_F) ? 0.f : __expf(mB - mn);
        float denom = dA * sA + dB * sB;
        float inv = 1.f / fmaxf(denom, 1e-16f);
        float4 acc;
        acc.x = (aA.x * sA + aB.x * sB) * inv;
        acc.y = (aA.y * sA + aB.y * sB) * inv;
        acc.z = (aA.z * sA + aB.z * sB) * inv;
        acc.w = (aA.w * sA + aB.w * sB) * inv;
        *(float4*)(g_bufOUT + (size_t)r * HD + lane * 4) = acc;
    }
}

// ---------------- final mean pool ----------------
__global__ void k_zero_out(float* out) {
    int t = threadIdx.x;
    if (t < 2 * HD) out[t] = 0.f;
}
__global__ void k_mean(float* __restrict__ out) {
    int col = threadIdx.x;                    // 128 threads
    float s = 0.f;
    for (int i = blockIdx.x; i < NND; i += gridDim.x)
        s += g_bufOUT[(size_t)i * HD + col];
    s *= (1.0f / NND);
    atomicAdd(&out[col], s);
    atomicAdd(&out[col + HD], s);
}

// ---------------- launch ----------------
extern "C" void kernel_launch(void* const* d_in, const int* in_sizes, int n_in,
                              void* d_out, int out_size) {
    const float* x   = (const float*)d_in[0];
    const int*   ei  = (const int*)d_in[1];     // int32 (JAX x64 disabled)
    int E = in_sizes[1] / 2;
    const int* row = ei;
    const int* col = ei + E;
    const float* Wg[3] = {(const float*)d_in[2], (const float*)d_in[6],  (const float*)d_in[10]};
    const float* bg[3] = {(const float*)d_in[3], (const float*)d_in[7],  (const float*)d_in[11]};
    const float* Wa[3] = {(const float*)d_in[4], (const float*)d_in[8],  (const float*)d_in[12]};
    const float* ba[3] = {(const float*)d_in[5], (const float*)d_in[9],  (const float*)d_in[13]};
    float* out = (float*)d_out;

    __half *pXW, *pHH;
    float *pACC, *pOUT, *pDinv;
    cudaGetSymbolAddress((void**)&pXW,  g_bufXW);
    cudaGetSymbolAddress((void**)&pHH,  g_bufHH);
    cudaGetSymbolAddress((void**)&pACC, g_bufACC);
    cudaGetSymbolAddress((void**)&pOUT, g_bufOUT);
    cudaGetSymbolAddress((void**)&pDinv, g_dinv);

    const int TB = 256;
    int gN  = (NND + TB - 1) / TB;              // 157
    int gE  = (E + TB - 1) / TB;
    int gNw = (NND + 7) / 8;
    int gGemm = (NND + 127) / 128;              // 313

    k_deg_init<<<gN, TB>>>();
    k_deg_count<<<gE, TB>>>(row, E);
    k_scanA<<<gN, TB>>>();                      // also computes dinv
    k_scanB<<<1, TB>>>(gN);
    k_scanC<<<gN, TB>>>();
    k_fill<<<gE, TB>>>(row, col, E);
    k_bperm_all<<<dim3(64, 6), TB>>>(Wg[0], Wa[0], Wg[1], Wa[1], Wg[2], Wa[2]);

    const float* cur = x;
    for (int l = 0; l < 3; l++) {
        k_gemm_tf32<<<gGemm, TB>>>(cur, nullptr, pDinv, pXW, NND, 2 * l);     // xwS = xw*dinv
        k_gcn<<<gNw, TB>>>(bg[l]);
        k_gemm_tf32<<<gGemm, TB>>>(pACC, ba[l], nullptr, pHH, NND, 2 * l + 1);
        k_gat<<<gNw, TB>>>();
        cur = pOUT;
    }
    k_zero_out<<<1, TB>>>(out);
    k_mean<<<512, HD>>>(out);
}

// round 10
// speedup vs baseline: 1.0150x; 1.0150x over previous
#include <cuda_runtime.h>
#include <cuda_fp16.h>
#include <cstdint>
#include <math_constants.h>

#define NND 40000
#define HD  128
#define EED 640000

// ---------------- scratch (device globals: allocation-free) ----------------
__device__ __half   g_bufXW [(size_t)NND * HD];   // GCN GEMM out, fp16 (gathered)
__device__ __half   g_bufHH [(size_t)NND * HD];   // GAT GEMM out, fp16 (gathered)
__device__ float    g_bufACC[(size_t)NND * HD];   // relu(GCN) out, fp32 (GEMM input)
__device__ float    g_bufOUT[(size_t)NND * HD];   // GAT out, fp32 (GEMM input / pool)
__device__ int      g_deg   [NND];
__device__ float    g_dinv  [NND];
__device__ int      g_rowptr[NND];
__device__ int      g_cursor[NND];
__device__ int      g_rowtmp[NND];
__device__ int      g_bsum  [256];
__device__ int      g_boff  [256];
__device__ int      g_csrcol[EED];
__device__ uint32_t g_Bperm [6 * HD * HD];        // 6 permuted weights (all layers)

// ---------------- helpers ----------------
__device__ __forceinline__ float4 h8_to_f4(uint2 u) {
    __half2 a = *(__half2*)&u.x, b = *(__half2*)&u.y;
    float2 fa = __half22float2(a), fb = __half22float2(b);
    return make_float4(fa.x, fa.y, fb.x, fb.y);
}

// ---------------- degree / norm ----------------
__global__ void k_deg_init() {
    int i = blockIdx.x * blockDim.x + threadIdx.x;
    if (i < NND) g_deg[i] = 1;
}
__global__ void k_deg_count(const int* __restrict__ row, int E) {
    int e = blockIdx.x * blockDim.x + threadIdx.x;
    if (e < E) atomicAdd(&g_deg[row[e]], 1);
}

// ---------------- hierarchical exclusive scan of (deg-1), + dinv ----------------
__global__ __launch_bounds__(256) void k_scanA() {
    __shared__ int sm[256];
    int tx = threadIdx.x;
    int i = blockIdx.x * 256 + tx;
    int d = (i < NND) ? g_deg[i] : 1;
    if (i < NND) g_dinv[i] = rsqrtf((float)d);
    int v = d - 1;
    if (i >= NND) v = 0;
    sm[tx] = v;
    __syncthreads();
#pragma unroll
    for (int off = 1; off < 256; off <<= 1) {
        int p = (tx >= off) ? sm[tx - off] : 0;
        __syncthreads();
        sm[tx] += p;
        __syncthreads();
    }
    if (i < NND) g_rowtmp[i] = sm[tx] - v;
    if (tx == 255) g_bsum[blockIdx.x] = sm[255];
}
__global__ __launch_bounds__(256) void k_scanB(int nb) {
    __shared__ int sm[256];
    int tx = threadIdx.x;
    int v = (tx < nb) ? g_bsum[tx] : 0;
    sm[tx] = v;
    __syncthreads();
#pragma unroll
    for (int off = 1; off < 256; off <<= 1) {
        int p = (tx >= off) ? sm[tx - off] : 0;
        __syncthreads();
        sm[tx] += p;
        __syncthreads();
    }
    g_boff[tx] = sm[tx] - v;
}
__global__ void k_scanC() {
    int i = blockIdx.x * blockDim.x + threadIdx.x;
    if (i < NND) {
        int rp = g_rowtmp[i] + g_boff[i >> 8];
        g_rowptr[i] = rp;
        g_cursor[i] = rp;
    }
}
__global__ void k_fill(const int* __restrict__ row, const int* __restrict__ col, int E) {
    int e = blockIdx.x * blockDim.x + threadIdx.x;
    if (e >= E) return;
    int r = row[e];
    int pos = atomicAdd(&g_cursor[r], 1);
    g_csrcol[pos] = col[e];
}

// ---------------- all-weights preconvert: (fold) + tf32 + fragment permute ----------
__device__ __forceinline__ uint32_t f2tf32(float f) {
    uint32_t u;
    asm("cvt.rna.tf32.f32 %0, %1;" : "=r"(u) : "f"(f));
    return u;
}
// slot s: 0..5 = Wg0,Wa0,Wg1,Wa1,Wg2,Wa2 ; fold for slots 2,4 (Wg1,Wg2)
__global__ void k_bperm_all(const float* __restrict__ W0, const float* __restrict__ W1,
                            const float* __restrict__ W2, const float* __restrict__ W3,
                            const float* __restrict__ W4, const float* __restrict__ W5) {
    int s = blockIdx.y;
    const float* W;
    int fold = 0;
    switch (s) {
        case 0: W = W0; break;
        case 1: W = W1; break;
        case 2: W = W2; fold = 1; break;
        case 3: W = W3; break;
        case 4: W = W4; fold = 1; break;
        default: W = W5; break;
    }
    int t = blockIdx.x * blockDim.x + threadIdx.x;
    if (t >= HD * HD) return;
    int k = t >> 7, n = t & 127;
    float v = W[t];
    if (fold) v += W[t + HD * HD];
    int ki = k >> 3, ni = n >> 3, kk = k & 7, nn = n & 7;
    int l = (nn << 2) | (kk & 3);
    int j = kk >> 2;
    g_Bperm[s * HD * HD + (ki * 16 + ni) * 64 + l * 2 + j] = f2tf32(v);
}

// ---------------- TF32 tensor-core GEMM: Ch[M,128] = A[M,128] @ Bperm[slot] ---------
__device__ __forceinline__ void mma_tf32(float* d, const uint32_t* a, const uint32_t* b) {
    asm volatile(
        "mma.sync.aligned.m16n8k8.row.col.f32.tf32.tf32.f32 "
        "{%0,%1,%2,%3}, {%4,%5,%6,%7}, {%8,%9}, {%0,%1,%2,%3};"
        : "+f"(d[0]), "+f"(d[1]), "+f"(d[2]), "+f"(d[3])
        : "r"(a[0]), "r"(a[1]), "r"(a[2]), "r"(a[3]), "r"(b[0]), "r"(b[1]));
}
__global__ __launch_bounds__(256) void k_gemm_tf32(const float* __restrict__ A,
                                                   const float* __restrict__ bias,
                                                   const float* __restrict__ rowscale,
                                                   __half* __restrict__ Ch, int M, int slot) {
    __shared__ uint32_t Asp[32 * 128];
    const uint32_t* Bp = g_Bperm + slot * HD * HD;
    int tid = threadIdx.x;
    int lane = tid & 31;
    int w = tid >> 5;
    int wm = w >> 2, wn = w & 3;
    int gRow0 = blockIdx.x * 128;
    float acc[4][4][4];
#pragma unroll
    for (int i = 0; i < 4; i++)
#pragma unroll
        for (int t = 0; t < 4; t++)
#pragma unroll
            for (int u = 0; u < 4; u++) acc[i][t][u] = 0.f;

    for (int kk = 0; kk < 128; kk += 32) {
#pragma unroll
        for (int q = 0; q < 4; q++) {
            int fid = tid + q * 256;
            int row = fid >> 3;
            int c4  = fid & 7;
            int gr  = gRow0 + row;
            float4 v = make_float4(0.f, 0.f, 0.f, 0.f);
            if (gr < M) v = *(const float4*)(A + (size_t)gr * 128 + kk + c4 * 4);
            int mi = row >> 4, rr = row & 15;
            int ki = c4 >> 1;
            int j  = (rr >> 3) | ((c4 & 1) << 1);
            uint4 o;
            o.x = f2tf32(v.x); o.y = f2tf32(v.y); o.z = f2tf32(v.z); o.w = f2tf32(v.w);
            *(uint4*)(&Asp[(ki * 8 + mi) * 128 + j * 32 + (rr & 7) * 4]) = o;
        }
        __syncthreads();
#pragma unroll
        for (int ki = 0; ki < 4; ki++) {
            uint32_t af[4][4];
#pragma unroll
            for (int i = 0; i < 4; i++) {
                const uint32_t* base = &Asp[(ki * 8 + wm * 4 + i) * 128];
                af[i][0] = base[lane];
                af[i][1] = base[32 + lane];
                af[i][2] = base[64 + lane];
                af[i][3] = base[96 + lane];
            }
            uint32_t bf[4][2];
            int kig = (kk >> 3) + ki;
#pragma unroll
            for (int t = 0; t < 4; t++) {
                uint2 b2 = *(const uint2*)(&Bp[(kig * 16 + wn * 4 + t) * 64 + lane * 2]);
                bf[t][0] = b2.x; bf[t][1] = b2.y;
            }
#pragma unroll
            for (int i = 0; i < 4; i++)
#pragma unroll
                for (int t = 0; t < 4; t++) mma_tf32(acc[i][t], af[i], bf[t]);
        }
        __syncthreads();
    }
    int g = lane >> 2, t4 = lane & 3;
#pragma unroll
    for (int i = 0; i < 4; i++) {
        int row0 = gRow0 + (wm * 4 + i) * 16 + g;
        int row1 = row0 + 8;
        float rs0 = 1.f, rs1 = 1.f;
        if (rowscale) {
            if (row0 < M) rs0 = rowscale[row0];
            if (row1 < M) rs1 = rowscale[row1];
        }
#pragma unroll
        for (int t = 0; t < 4; t++) {
            int col = (wn * 4 + t) * 8 + 2 * t4;
            float b0 = bias ? bias[col] : 0.f;
            float b1 = bias ? bias[col + 1] : 0.f;
            if (row0 < M)
                *(__half2*)(Ch + (size_t)row0 * 128 + col) =
                    __floats2half2_rn((acc[i][t][0] + b0) * rs0, (acc[i][t][1] + b1) * rs0);
            if (row1 < M)
                *(__half2*)(Ch + (size_t)row1 * 128 + col) =
                    __floats2half2_rn((acc[i][t][2] + b0) * rs1, (acc[i][t][3] + b1) * rs1);
        }
    }
}

// ---------------- fused GCN (warp per node, CSR, fp16 gathered, fp32 accum) ---------
// (exact R8 version)
__global__ __launch_bounds__(256) void k_gcn(const float* __restrict__ bias) {
    int r = (blockIdx.x * blockDim.x + threadIdx.x) >> 5;
    int lane = threadIdx.x & 31;
    if (r >= NND) return;
    int beg = g_rowptr[r];
    int cnt = g_deg[r] - 1;
    float dr = g_dinv[r];
    const __half* xw = g_bufXW;
    float4 acc = h8_to_f4(*(const uint2*)(xw + (size_t)r * HD + lane * 4));
    int j = 0;
    for (; j + 8 <= cnt; j += 8) {
        uint2 u[8];
#pragma unroll
        for (int q = 0; q < 8; q++) {
            int c = g_csrcol[beg + j + q];
            u[q] = *(const uint2*)(xw + (size_t)c * HD + lane * 4);
        }
#pragma unroll
        for (int q = 0; q < 8; q++) {
            float4 v = h8_to_f4(u[q]);
            acc.x += v.x; acc.y += v.y; acc.z += v.z; acc.w += v.w;
        }
    }
    for (; j < cnt; j++) {
        int c = g_csrcol[beg + j];
        float4 v = h8_to_f4(*(const uint2*)(xw + (size_t)c * HD + lane * 4));
        acc.x += v.x; acc.y += v.y; acc.z += v.z; acc.w += v.w;
    }
    float4 b = *(const float4*)(bias + lane * 4);
    acc.x = fmaxf(acc.x * dr + b.x, 0.f);
    acc.y = fmaxf(acc.y * dr + b.y, 0.f);
    acc.z = fmaxf(acc.z * dr + b.z, 0.f);
    acc.w = fmaxf(acc.w * dr + b.w, 0.f);
    *(float4*)(g_bufACC + (size_t)r * HD + lane * 4) = acc;
}

// ---------------- fused GAT: online softmax with LAZY RESCALE (warp per node) -------
__device__ __forceinline__ float warp_sum(float s) {
#pragma unroll
    for (int o = 16; o; o >>= 1) s += __shfl_xor_sync(0xffffffffu, s, o);
    return s;
}
__global__ __launch_bounds__(256) void k_gat() {
    int r = (blockIdx.x * blockDim.x + threadIdx.x) >> 5;
    int lane = threadIdx.x & 31;
    if (r >= NND) return;
    int beg = g_rowptr[r];
    int cnt = g_deg[r] - 1;
    const __half* hh = g_bufHH;
    float4 hr = h8_to_f4(*(const uint2*)(hh + (size_t)r * HD + lane * 4));
    float m = warp_sum(hr.x * hr.x + hr.y * hr.y + hr.z * hr.z + hr.w * hr.w);
    float denom = 1.f;
    float4 acc = hr;
    int j = 0;
    for (; j + 4 <= cnt; j += 4) {
        int c0 = g_csrcol[beg + j];
        int c1 = g_csrcol[beg + j + 1];
        int c2 = g_csrcol[beg + j + 2];
        int c3 = g_csrcol[beg + j + 3];
        float4 h0 = h8_to_f4(*(const uint2*)(hh + (size_t)c0 * HD + lane * 4));
        float4 h1 = h8_to_f4(*(const uint2*)(hh + (size_t)c1 * HD + lane * 4));
        float4 h2 = h8_to_f4(*(const uint2*)(hh + (size_t)c2 * HD + lane * 4));
        float4 h3 = h8_to_f4(*(const uint2*)(hh + (size_t)c3 * HD + lane * 4));
        float d0 = hr.x * h0.x + hr.y * h0.y + hr.z * h0.z + hr.w * h0.w;
        float d1 = hr.x * h1.x + hr.y * h1.y + hr.z * h1.z + hr.w * h1.w;
        float d2 = hr.x * h2.x + hr.y * h2.y + hr.z * h2.z + hr.w * h2.w;
        float d3 = hr.x * h3.x + hr.y * h3.y + hr.z * h3.z + hr.w * h3.w;
#pragma unroll
        for (int o = 16; o; o >>= 1) {
            d0 += __shfl_xor_sync(0xffffffffu, d0, o);
            d1 += __shfl_xor_sync(0xffffffffu, d1, o);
            d2 += __shfl_xor_sync(0xffffffffu, d2, o);
            d3 += __shfl_xor_sync(0xffffffffu, d3, o);
        }
        float a0 = (c0 == r) ? -CUDART_INF_F : ((d0 > 0.f) ? d0 : 0.2f * d0);
        float a1 = (c1 == r) ? -CUDART_INF_F : ((d1 > 0.f) ? d1 : 0.2f * d1);
        float a2 = (c2 == r) ? -CUDART_INF_F : ((d2 > 0.f) ? d2 : 0.2f * d2);
        float a3 = (c3 == r) ? -CUDART_INF_F : ((d3 > 0.f) ? d3 : 0.2f * d3);
        float mblk = fmaxf(fmaxf(a0, a1), fmaxf(a2, a3));
        if (mblk > m) {                        // warp-uniform, rare (~E[ln deg]/deg)
            float s = __expf(m - mblk);
            denom *= s;
            acc.x *= s; acc.y *= s; acc.z *= s; acc.w *= s;
            m = mblk;
        }
        float e0 = __expf(a0 - m);
        float e1 = __expf(a1 - m);
        float e2 = __expf(a2 - m);
        float e3 = __expf(a3 - m);
        denom += (e0 + e1) + (e2 + e3);
        acc.x += (e0 * h0.x + e1 * h1.x) + (e2 * h2.x + e3 * h3.x);
        acc.y += (e0 * h0.y + e1 * h1.y) + (e2 * h2.y + e3 * h3.y);
        acc.z += (e0 * h0.z + e1 * h1.z) + (e2 * h2.z + e3 * h3.z);
        acc.w += (e0 * h0.w + e1 * h1.w) + (e2 * h2.w + e3 * h3.w);
    }
    for (; j < cnt; j++) {
        int c = g_csrcol[beg + j];
        if (c == r) continue;
        float4 hc = h8_to_f4(*(const uint2*)(hh + (size_t)c * HD + lane * 4));
        float d = warp_sum(hr.x * hc.x + hr.y * hc.y + hr.z * hc.z + hr.w * hc.w);
        float al = (d > 0.f) ? d : 0.2f * d;
        if (al > m) {
            float s = __expf(m - al);
            denom *= s;
            acc.x *= s; acc.y *= s; acc.z *= s; acc.w *= s;
            m = al;
        }
        float e = __expf(al - m);
        denom += e;
        acc.x += e * hc.x;
        acc.y += e * hc.y;
        acc.z += e * hc.z;
        acc.w += e * hc.w;
    }
    float inv = 1.f / fmaxf(denom, 1e-16f);
    acc.x *= inv; acc.y *= inv; acc.z *= inv; acc.w *= inv;
    *(float4*)(g_bufOUT + (size_t)r * HD + lane * 4) = acc;
}

// ---------------- final mean pool ----------------
__global__ void k_zero_out(float* out) {
    int t = threadIdx.x;
    if (t < 2 * HD) out[t] = 0.f;
}
__global__ void k_mean(float* __restrict__ out) {
    int col = threadIdx.x;                    // 128 threads
    float s = 0.f;
    for (int i = blockIdx.x; i < NND; i += gridDim.x)
        s += g_bufOUT[(size_t)i * HD + col];
    s *= (1.0f / NND);
    atomicAdd(&out[col], s);
    atomicAdd(&out[col + HD], s);
}

// ---------------- launch ----------------
extern "C" void kernel_launch(void* const* d_in, const int* in_sizes, int n_in,
                              void* d_out, int out_size) {
    const float* x   = (const float*)d_in[0];
    const int*   ei  = (const int*)d_in[1];     // int32 (JAX x64 disabled)
    int E = in_sizes[1] / 2;
    const int* row = ei;
    const int* col = ei + E;
    const float* Wg[3] = {(const float*)d_in[2], (const float*)d_in[6],  (const float*)d_in[10]};
    const float* bg[3] = {(const float*)d_in[3], (const float*)d_in[7],  (const float*)d_in[11]};
    const float* Wa[3] = {(const float*)d_in[4], (const float*)d_in[8],  (const float*)d_in[12]};
    const float* ba[3] = {(const float*)d_in[5], (const float*)d_in[9],  (const float*)d_in[13]};
    float* out = (float*)d_out;

    __half *pXW, *pHH;
    float *pACC, *pOUT, *pDinv;
    cudaGetSymbolAddress((void**)&pXW,  g_bufXW);
    cudaGetSymbolAddress((void**)&pHH,  g_bufHH);
    cudaGetSymbolAddress((void**)&pACC, g_bufACC);
    cudaGetSymbolAddress((void**)&pOUT, g_bufOUT);
    cudaGetSymbolAddress((void**)&pDinv, g_dinv);

    const int TB = 256;
    int gN  = (NND + TB - 1) / TB;              // 157
    int gE  = (E + TB - 1) / TB;
    int gNw = (NND + 7) / 8;
    int gGemm = (NND + 127) / 128;              // 313

    k_deg_init<<<gN, TB>>>();
    k_deg_count<<<gE, TB>>>(row, E);
    k_scanA<<<gN, TB>>>();                      // also computes dinv
    k_scanB<<<1, TB>>>(gN);
    k_scanC<<<gN, TB>>>();
    k_fill<<<gE, TB>>>(row, col, E);
    k_bperm_all<<<dim3(64, 6), TB>>>(Wg[0], Wa[0], Wg[1], Wa[1], Wg[2], Wa[2]);

    const float* cur = x;
    for (int l = 0; l < 3; l++) {
        k_gemm_tf32<<<gGemm, TB>>>(cur, nullptr, pDinv, pXW, NND, 2 * l);     // xwS = xw*dinv
        k_gcn<<<gNw, TB>>>(bg[l]);
        k_gemm_tf32<<<gGemm, TB>>>(pACC, ba[l], nullptr, pHH, NND, 2 * l + 1);
        k_gat<<<gNw, TB>>>();
        cur = pOUT;
    }
    k_zero_out<<<1, TB>>>(out);
    k_mean<<<512, HD>>>(out);
}

// round 11
// speedup vs baseline: 1.0990x; 1.0828x over previous
#include <cuda_runtime.h>
#include <cuda_fp16.h>
#include <cstdint>
#include <math_constants.h>

#define NND 40000
#define HD  128
#define EED 640000

// ---------------- scratch (device globals: allocation-free) ----------------
__device__ __half   g_bufXW [(size_t)NND * HD];   // GCN GEMM out, fp16 (gathered)
__device__ __half   g_bufHH [(size_t)NND * HD];   // GAT GEMM out, fp16 (gathered)
__device__ float    g_bufACC[(size_t)NND * HD];   // relu(GCN) out, fp32 (GEMM input)
__device__ float    g_bufOUT[(size_t)NND * HD];   // GAT out, fp32 (GEMM input / pool)
__device__ int      g_deg   [NND];
__device__ float    g_dinv  [NND];
__device__ int      g_rowptr[NND];
__device__ int      g_cursor[NND];
__device__ int      g_rowtmp[NND];
__device__ int      g_bsum  [256];
__device__ int      g_boff  [256];
__device__ int      g_csrcol[EED];
__device__ uint32_t g_Bperm [HD * HD];

// ---------------- helpers ----------------
__device__ __forceinline__ float4 h8_to_f4(uint2 u) {
    __half2 a = *(__half2*)&u.x, b = *(__half2*)&u.y;
    float2 fa = __half22float2(a), fb = __half22float2(b);
    return make_float4(fa.x, fa.y, fb.x, fb.y);
}

// ---------------- degree / norm ----------------
__global__ void k_deg_init() {
    int i = blockIdx.x * blockDim.x + threadIdx.x;
    if (i < NND) g_deg[i] = 1;
}
__global__ void k_deg_count(const int* __restrict__ row, int E) {
    int e = blockIdx.x * blockDim.x + threadIdx.x;
    if (e < E) atomicAdd(&g_deg[row[e]], 1);
}

// ---------------- hierarchical exclusive scan of (deg-1), + dinv ----------------
__global__ __launch_bounds__(256) void k_scanA() {
    __shared__ int sm[256];
    int tx = threadIdx.x;
    int i = blockIdx.x * 256 + tx;
    int d = (i < NND) ? g_deg[i] : 1;
    if (i < NND) g_dinv[i] = rsqrtf((float)d);
    int v = d - 1;
    if (i >= NND) v = 0;
    sm[tx] = v;
    __syncthreads();
#pragma unroll
    for (int off = 1; off < 256; off <<= 1) {
        int p = (tx >= off) ? sm[tx - off] : 0;
        __syncthreads();
        sm[tx] += p;
        __syncthreads();
    }
    if (i < NND) g_rowtmp[i] = sm[tx] - v;
    if (tx == 255) g_bsum[blockIdx.x] = sm[255];
}
__global__ __launch_bounds__(256) void k_scanB(int nb) {
    __shared__ int sm[256];
    int tx = threadIdx.x;
    int v = (tx < nb) ? g_bsum[tx] : 0;
    sm[tx] = v;
    __syncthreads();
#pragma unroll
    for (int off = 1; off < 256; off <<= 1) {
        int p = (tx >= off) ? sm[tx - off] : 0;
        __syncthreads();
        sm[tx] += p;
        __syncthreads();
    }
    g_boff[tx] = sm[tx] - v;
}
__global__ void k_scanC() {
    int i = blockIdx.x * blockDim.x + threadIdx.x;
    if (i < NND) {
        int rp = g_rowtmp[i] + g_boff[i >> 8];
        g_rowptr[i] = rp;
        g_cursor[i] = rp;
    }
}
__global__ void k_fill(const int* __restrict__ row, const int* __restrict__ col, int E) {
    int e = blockIdx.x * blockDim.x + threadIdx.x;
    if (e >= E) return;
    int r = row[e];
    int pos = atomicAdd(&g_cursor[r], 1);
    g_csrcol[pos] = col[e];
}

// ---------------- weight preconvert: (fold) + tf32 + fragment permute ----------------
__device__ __forceinline__ uint32_t f2tf32(float f) {
    uint32_t u;
    asm("cvt.rna.tf32.f32 %0, %1;" : "=r"(u) : "f"(f));
    return u;
}
__global__ void k_bperm(const float* __restrict__ W, int fold) {
    int t = blockIdx.x * blockDim.x + threadIdx.x;
    if (t >= HD * HD) return;
    int k = t >> 7, n = t & 127;
    float v = W[t];
    if (fold) v += W[t + HD * HD];
    int ki = k >> 3, ni = n >> 3, kk = k & 7, nn = n & 7;
    int l = (nn << 2) | (kk & 3);
    int j = kk >> 2;
    g_Bperm[(ki * 16 + ni) * 64 + l * 2 + j] = f2tf32(v);
}

// ---------------- TF32 tensor-core GEMM: Ch[M,128] = A[M,128] @ Bperm (fp16 out) ----
__device__ __forceinline__ void mma_tf32(float* d, const uint32_t* a, const uint32_t* b) {
    asm volatile(
        "mma.sync.aligned.m16n8k8.row.col.f32.tf32.tf32.f32 "
        "{%0,%1,%2,%3}, {%4,%5,%6,%7}, {%8,%9}, {%0,%1,%2,%3};"
        : "+f"(d[0]), "+f"(d[1]), "+f"(d[2]), "+f"(d[3])
        : "r"(a[0]), "r"(a[1]), "r"(a[2]), "r"(a[3]), "r"(b[0]), "r"(b[1]));
}
__global__ __launch_bounds__(256) void k_gemm_tf32(const float* __restrict__ A,
                                                   const float* __restrict__ bias,
                                                   const float* __restrict__ rowscale,
                                                   __half* __restrict__ Ch, int M) {
    __shared__ uint32_t Asp[32 * 128];
    int tid = threadIdx.x;
    int lane = tid & 31;
    int w = tid >> 5;
    int wm = w >> 2, wn = w & 3;
    int gRow0 = blockIdx.x * 128;
    float acc[4][4][4];
#pragma unroll
    for (int i = 0; i < 4; i++)
#pragma unroll
        for (int t = 0; t < 4; t++)
#pragma unroll
            for (int u = 0; u < 4; u++) acc[i][t][u] = 0.f;

    for (int kk = 0; kk < 128; kk += 32) {
#pragma unroll
        for (int q = 0; q < 4; q++) {
            int fid = tid + q * 256;
            int row = fid >> 3;
            int c4  = fid & 7;
            int gr  = gRow0 + row;
            float4 v = make_float4(0.f, 0.f, 0.f, 0.f);
            if (gr < M) v = *(const float4*)(A + (size_t)gr * 128 + kk + c4 * 4);
            int mi = row >> 4, rr = row & 15;
            int ki = c4 >> 1;
            int j  = (rr >> 3) | ((c4 & 1) << 1);
            uint4 o;
            o.x = f2tf32(v.x); o.y = f2tf32(v.y); o.z = f2tf32(v.z); o.w = f2tf32(v.w);
            *(uint4*)(&Asp[(ki * 8 + mi) * 128 + j * 32 + (rr & 7) * 4]) = o;
        }
        __syncthreads();
#pragma unroll
        for (int ki = 0; ki < 4; ki++) {
            uint32_t af[4][4];
#pragma unroll
            for (int i = 0; i < 4; i++) {
                const uint32_t* base = &Asp[(ki * 8 + wm * 4 + i) * 128];
                af[i][0] = base[lane];
                af[i][1] = base[32 + lane];
                af[i][2] = base[64 + lane];
                af[i][3] = base[96 + lane];
            }
            uint32_t bf[4][2];
            int kig = (kk >> 3) + ki;
#pragma unroll
            for (int t = 0; t < 4; t++) {
                uint2 b2 = *(const uint2*)(&g_Bperm[(kig * 16 + wn * 4 + t) * 64 + lane * 2]);
                bf[t][0] = b2.x; bf[t][1] = b2.y;
            }
#pragma unroll
            for (int i = 0; i < 4; i++)
#pragma unroll
                for (int t = 0; t < 4; t++) mma_tf32(acc[i][t], af[i], bf[t]);
        }
        __syncthreads();
    }
    int g = lane >> 2, t4 = lane & 3;
#pragma unroll
    for (int i = 0; i < 4; i++) {
        int row0 = gRow0 + (wm * 4 + i) * 16 + g;
        int row1 = row0 + 8;
        float rs0 = 1.f, rs1 = 1.f;
        if (rowscale) {
            if (row0 < M) rs0 = rowscale[row0];
            if (row1 < M) rs1 = rowscale[row1];
        }
#pragma unroll
        for (int t = 0; t < 4; t++) {
            int col = (wn * 4 + t) * 8 + 2 * t4;
            float b0 = bias ? bias[col] : 0.f;
            float b1 = bias ? bias[col + 1] : 0.f;
            if (row0 < M)
                *(__half2*)(Ch + (size_t)row0 * 128 + col) =
                    __floats2half2_rn((acc[i][t][0] + b0) * rs0, (acc[i][t][1] + b1) * rs0);
            if (row1 < M)
                *(__half2*)(Ch + (size_t)row1 * 128 + col) =
                    __floats2half2_rn((acc[i][t][2] + b0) * rs1, (acc[i][t][3] + b1) * rs1);
        }
    }
}

// ---------------- fused GCN (warp per node, CSR, fp16 gathered, fp32 accum) ---------
// (exact R8 version)
__global__ __launch_bounds__(256) void k_gcn(const float* __restrict__ bias) {
    int r = (blockIdx.x * blockDim.x + threadIdx.x) >> 5;
    int lane = threadIdx.x & 31;
    if (r >= NND) return;
    int beg = g_rowptr[r];
    int cnt = g_deg[r] - 1;
    float dr = g_dinv[r];
    const __half* xw = g_bufXW;
    float4 acc = h8_to_f4(*(const uint2*)(xw + (size_t)r * HD + lane * 4));
    int j = 0;
    for (; j + 8 <= cnt; j += 8) {
        uint2 u[8];
#pragma unroll
        for (int q = 0; q < 8; q++) {
            int c = g_csrcol[beg + j + q];
            u[q] = *(const uint2*)(xw + (size_t)c * HD + lane * 4);
        }
#pragma unroll
        for (int q = 0; q < 8; q++) {
            float4 v = h8_to_f4(u[q]);
            acc.x += v.x; acc.y += v.y; acc.z += v.z; acc.w += v.w;
        }
    }
    for (; j < cnt; j++) {
        int c = g_csrcol[beg + j];
        float4 v = h8_to_f4(*(const uint2*)(xw + (size_t)c * HD + lane * 4));
        acc.x += v.x; acc.y += v.y; acc.z += v.z; acc.w += v.w;
    }
    float4 b = *(const float4*)(bias + lane * 4);
    acc.x = fmaxf(acc.x * dr + b.x, 0.f);
    acc.y = fmaxf(acc.y * dr + b.y, 0.f);
    acc.z = fmaxf(acc.z * dr + b.z, 0.f);
    acc.w = fmaxf(acc.w * dr + b.w, 0.f);
    *(float4*)(g_bufACC + (size_t)r * HD + lane * 4) = acc;
}

// ---------------- fused GAT: online softmax with LAZY RESCALE (warp per node) -------
__device__ __forceinline__ float warp_sum(float s) {
#pragma unroll
    for (int o = 16; o; o >>= 1) s += __shfl_xor_sync(0xffffffffu, s, o);
    return s;
}
__global__ __launch_bounds__(256) void k_gat() {
    int r = (blockIdx.x * blockDim.x + threadIdx.x) >> 5;
    int lane = threadIdx.x & 31;
    if (r >= NND) return;
    int beg = g_rowptr[r];
    int cnt = g_deg[r] - 1;
    const __half* hh = g_bufHH;
    float4 hr = h8_to_f4(*(const uint2*)(hh + (size_t)r * HD + lane * 4));
    float m = warp_sum(hr.x * hr.x + hr.y * hr.y + hr.z * hr.z + hr.w * hr.w);
    float denom = 1.f;
    float4 acc = hr;
    int j = 0;
    for (; j + 4 <= cnt; j += 4) {
        int c0 = g_csrcol[beg + j];
        int c1 = g_csrcol[beg + j + 1];
        int c2 = g_csrcol[beg + j + 2];
        int c3 = g_csrcol[beg + j + 3];
        float4 h0 = h8_to_f4(*(const uint2*)(hh + (size_t)c0 * HD + lane * 4));
        float4 h1 = h8_to_f4(*(const uint2*)(hh + (size_t)c1 * HD + lane * 4));
        float4 h2 = h8_to_f4(*(const uint2*)(hh + (size_t)c2 * HD + lane * 4));
        float4 h3 = h8_to_f4(*(const uint2*)(hh + (size_t)c3 * HD + lane * 4));
        float d0 = hr.x * h0.x + hr.y * h0.y + hr.z * h0.z + hr.w * h0.w;
        float d1 = hr.x * h1.x + hr.y * h1.y + hr.z * h1.z + hr.w * h1.w;
        float d2 = hr.x * h2.x + hr.y * h2.y + hr.z * h2.z + hr.w * h2.w;
        float d3 = hr.x * h3.x + hr.y * h3.y + hr.z * h3.z + hr.w * h3.w;
#pragma unroll
        for (int o = 16; o; o >>= 1) {
            d0 += __shfl_xor_sync(0xffffffffu, d0, o);
            d1 += __shfl_xor_sync(0xffffffffu, d1, o);
            d2 += __shfl_xor_sync(0xffffffffu, d2, o);
            d3 += __shfl_xor_sync(0xffffffffu, d3, o);
        }
        float a0 = (c0 == r) ? -CUDART_INF_F : ((d0 > 0.f) ? d0 : 0.2f * d0);
        float a1 = (c1 == r) ? -CUDART_INF_F : ((d1 > 0.f) ? d1 : 0.2f * d1);
        float a2 = (c2 == r) ? -CUDART_INF_F : ((d2 > 0.f) ? d2 : 0.2f * d2);
        float a3 = (c3 == r) ? -CUDART_INF_F : ((d3 > 0.f) ? d3 : 0.2f * d3);
        float mblk = fmaxf(fmaxf(a0, a1), fmaxf(a2, a3));
        if (mblk > m) {                        // warp-uniform, ~E[ln deg]/deg of blocks
            float s = __expf(m - mblk);
            denom *= s;
            acc.x *= s; acc.y *= s; acc.z *= s; acc.w *= s;
            m = mblk;
        }
        float e0 = __expf(a0 - m);
        float e1 = __expf(a1 - m);
        float e2 = __expf(a2 - m);
        float e3 = __expf(a3 - m);
        denom += (e0 + e1) + (e2 + e3);
        acc.x += (e0 * h0.x + e1 * h1.x) + (e2 * h2.x + e3 * h3.x);
        acc.y += (e0 * h0.y + e1 * h1.y) + (e2 * h2.y + e3 * h3.y);
        acc.z += (e0 * h0.z + e1 * h1.z) + (e2 * h2.z + e3 * h3.z);
        acc.w += (e0 * h0.w + e1 * h1.w) + (e2 * h2.w + e3 * h3.w);
    }
    for (; j < cnt; j++) {
        int c = g_csrcol[beg + j];
        if (c == r) continue;
        float4 hc = h8_to_f4(*(const uint2*)(hh + (size_t)c * HD + lane * 4));
        float d = warp_sum(hr.x * hc.x + hr.y * hc.y + hr.z * hc.z + hr.w * hc.w);
        float al = (d > 0.f) ? d : 0.2f * d;
        if (al > m) {
            float s = __expf(m - al);
            denom *= s;
            acc.x *= s; acc.y *= s; acc.z *= s; acc.w *= s;
            m = al;
        }
        float e = __expf(al - m);
        denom += e;
        acc.x += e * hc.x;
        acc.y += e * hc.y;
        acc.z += e * hc.z;
        acc.w += e * hc.w;
    }
    float inv = 1.f / fmaxf(denom, 1e-16f);
    acc.x *= inv; acc.y *= inv; acc.z *= inv; acc.w *= inv;
    *(float4*)(g_bufOUT + (size_t)r * HD + lane * 4) = acc;
}

// ---------------- final mean pool ----------------
__global__ void k_zero_out(float* out) {
    int t = threadIdx.x;
    if (t < 2 * HD) out[t] = 0.f;
}
__global__ void k_mean(float* __restrict__ out) {
    int col = threadIdx.x;                    // 128 threads
    float s = 0.f;
    for (int i = blockIdx.x; i < NND; i += gridDim.x)
        s += g_bufOUT[(size_t)i * HD + col];
    s *= (1.0f / NND);
    atomicAdd(&out[col], s);
    atomicAdd(&out[col + HD], s);
}

// ---------------- launch ----------------
extern "C" void kernel_launch(void* const* d_in, const int* in_sizes, int n_in,
                              void* d_out, int out_size) {
    const float* x   = (const float*)d_in[0];
    const int*   ei  = (const int*)d_in[1];     // int32 (JAX x64 disabled)
    int E = in_sizes[1] / 2;
    const int* row = ei;
    const int* col = ei + E;
    const float* Wg[3] = {(const float*)d_in[2], (const float*)d_in[6],  (const float*)d_in[10]};
    const float* bg[3] = {(const float*)d_in[3], (const float*)d_in[7],  (const float*)d_in[11]};
    const float* Wa[3] = {(const float*)d_in[4], (const float*)d_in[8],  (const float*)d_in[12]};
    const float* ba[3] = {(const float*)d_in[5], (const float*)d_in[9],  (const float*)d_in[13]};
    float* out = (float*)d_out;

    __half *pXW, *pHH;
    float *pACC, *pOUT, *pDinv;
    cudaGetSymbolAddress((void**)&pXW,  g_bufXW);
    cudaGetSymbolAddress((void**)&pHH,  g_bufHH);
    cudaGetSymbolAddress((void**)&pACC, g_bufACC);
    cudaGetSymbolAddress((void**)&pOUT, g_bufOUT);
    cudaGetSymbolAddress((void**)&pDinv, g_dinv);

    const int TB = 256;
    int gN  = (NND + TB - 1) / TB;              // 157
    int gE  = (E + TB - 1) / TB;
    int gNw = (NND + 7) / 8;
    int gGemm = (NND + 127) / 128;              // 313

    k_deg_init<<<gN, TB>>>();
    k_deg_count<<<gE, TB>>>(row, E);
    k_scanA<<<gN, TB>>>();                      // also computes dinv
    k_scanB<<<1, TB>>>(gN);
    k_scanC<<<gN, TB>>>();
    k_fill<<<gE, TB>>>(row, col, E);

    const float* cur = x;
    for (int l = 0; l < 3; l++) {
        k_bperm<<<64, TB>>>(Wg[l], l > 0 ? 1 : 0);
        k_gemm_tf32<<<gGemm, TB>>>(cur, nullptr, pDinv, pXW, NND);   // xwS = xw * dinv
        k_gcn<<<gNw, TB>>>(bg[l]);
        k_bperm<<<64, TB>>>(Wa[l], 0);
        k_gemm_tf32<<<gGemm, TB>>>(pACC, ba[l], nullptr, pHH, NND);
        k_gat<<<gNw, TB>>>();
        cur = pOUT;
    }
    k_zero_out<<<1, TB>>>(out);
    k_mean<<<512, HD>>>(out);
}